// round 7
// baseline (speedup 1.0000x reference)
#include <cuda_runtime.h>
#include <cstdint>
#include <math.h>

#define KNBR  32
#define D     128
#define T     512
#define B_TOT 32768
#define NQUAD (B_TOT / 4)   // 4 rows (2 pairs) per macro-iteration

// smem layout (float offsets)
#define OFF_HN    0        // 2 * 16384 double-buffered (4 rows x 4096), thread-private regions
#define OFF_VS    32768    // 256 (v_ego | v_nbr)
#define OFF_EGO2  33024    // 512: ego2[pair*256 + 2*d + r]
#define OFF_AGG2  33536    // 512
#define OFF_REDD  34048    // 2048: 16 warps x 128
#define OFF_REDE  36096    // 2048: 2 pairs x 4 groups x 128 (float2)
#define OFF_LOG   38144    // 128
#define OFF_ATT   38272    // 128
#define SMEM_FLOATS 38400
#define SMEM_BYTES (SMEM_FLOATS * 4)

__device__ float g_v[2 * D];   // [0:128) v_ego = W_msg^T a_ego, [128:256) v_nbr

// ---------------- prologue: v = W_msg^T @ a ----------------
__global__ void prep_kernel(const float* __restrict__ Wmsg,
                            const float* __restrict__ Wattn) {
    int d = threadIdx.x;   // 128 threads
    float ve = 0.f, vn = 0.f;
    #pragma unroll 8
    for (int e = 0; e < D; e++) {
        float w = Wmsg[e * D + d];
        ve = fmaf(Wattn[e], w, ve);
        vn = fmaf(Wattn[D + e], w, vn);
    }
    g_v[d] = ve;
    g_v[D + d] = vn;
}

// ---------------- cp.async helpers ----------------
__device__ __forceinline__ void cp16(uint32_t dst, const void* src) {
    asm volatile("cp.async.cg.shared.global [%0], [%1], 16;" :: "r"(dst), "l"(src));
}
__device__ __forceinline__ void cp_commit() { asm volatile("cp.async.commit_group;"); }
__device__ __forceinline__ void cp_wait1()  { asm volatile("cp.async.wait_group 1;" ::: "memory"); }
__device__ __forceinline__ void cp_waitall(){ asm volatile("cp.async.wait_all;" ::: "memory"); }

// each thread copies EXACTLY the 8 fragments it will itself read later:
// rows (rr, kq..kq+7), column lane*4  -> producer == consumer, no CTA barrier
__device__ __forceinline__ void prefetch_own(int q, int buf, int rr, int kq, int lane,
                                             uint32_t smem_u32,
                                             const float* __restrict__ h_nei) {
    const float* src = h_nei + (size_t)q * 16384 + rr * 4096 + kq * 128 + lane * 4;
    uint32_t dst = smem_u32 +
        (uint32_t)(OFF_HN + buf * 16384 + rr * 4096 + kq * 128 + lane * 4) * 4u;
    #pragma unroll
    for (int i = 0; i < 8; i++)
        cp16(dst + (uint32_t)i * 512u, src + i * 128);
}

// ---------------- FFMA2 projection: 64 inputs, 2 rows packed, 4 acc chains ----------------
__device__ __forceinline__ void proj64(const unsigned long long* __restrict__ xq,
                                       const float* __restrict__ wreg,
                                       int d0, unsigned long long* dst) {
    unsigned long long acc0 = 0ull, acc1 = 0ull, acc2 = 0ull, acc3 = 0ull;
    #pragma unroll
    for (int j = 0; j < 64; j += 8) {
        #define PROJ_STEP(JJ, ACC) { \
            ulonglong2 xx = *(const ulonglong2*)&xq[d0 + (JJ)]; \
            unsigned long long w0, w1; \
            unsigned int wa = __float_as_uint(wreg[(JJ)]); \
            unsigned int wb = __float_as_uint(wreg[(JJ) + 1]); \
            asm("mov.b64 %0, {%1,%1};" : "=l"(w0) : "r"(wa)); \
            asm("mov.b64 %0, {%1,%1};" : "=l"(w1) : "r"(wb)); \
            asm("fma.rn.f32x2 %0, %1, %2, %3;" : "=l"(ACC) : "l"(w0), "l"(xx.x), "l"(ACC)); \
            asm("fma.rn.f32x2 %0, %1, %2, %3;" : "=l"(ACC) : "l"(w1), "l"(xx.y), "l"(ACC)); }
        PROJ_STEP(j,     acc0)
        PROJ_STEP(j + 2, acc1)
        PROJ_STEP(j + 4, acc2)
        PROJ_STEP(j + 6, acc3)
        #undef PROJ_STEP
    }
    asm("add.rn.f32x2 %0, %1, %2;" : "=l"(acc0) : "l"(acc0), "l"(acc1));
    asm("add.rn.f32x2 %0, %1, %2;" : "=l"(acc2) : "l"(acc2), "l"(acc3));
    asm("add.rn.f32x2 %0, %1, %2;" : "=l"(acc0) : "l"(acc0), "l"(acc2));
    *dst = acc0;
}

// ---------------- main fused kernel ----------------
__global__ void __launch_bounds__(T, 1)
gat_kernel(const float* __restrict__ h_ego, const float* __restrict__ h_nei,
           const int*   __restrict__ nbr_mask,
           const float* __restrict__ Wmsg, const float* __restrict__ Wself,
           const float* __restrict__ bself, float* __restrict__ out) {
    extern __shared__ float sm[];
    float* vs    = sm + OFF_VS;
    float* ego2  = sm + OFF_EGO2;
    float* agg2  = sm + OFF_AGG2;
    float* redD  = sm + OFF_REDD;
    float* redE  = sm + OFF_REDE;
    float* logit = sm + OFF_LOG;
    float* attn  = sm + OFF_ATT;

    const int tid  = threadIdx.x;
    const int lane = tid & 31;
    const int warp = tid >> 5;
    const int g    = tid >> 7;            // 0..3: {Wmsg-lo, Wmsg-hi, Wself-lo, Wself-hi}
    const int e    = tid & 127;
    const int d0   = (g & 1) * 64;        // input-dim half
    const int rr   = warp >> 2;           // row within quad (0..3)
    const int kq   = (warp & 3) * 8;      // 8 k's per warp

    // W slice in registers
    const float* Wsrc = (g < 2) ? Wmsg : Wself;
    float wreg[64];
    #pragma unroll
    for (int j = 0; j < 64; j += 4) {
        float4 t4 = *(const float4*)&Wsrc[e * D + d0 + j];
        wreg[j] = t4.x; wreg[j + 1] = t4.y; wreg[j + 2] = t4.z; wreg[j + 3] = t4.w;
    }
    if (tid < 2 * D) vs[tid] = g_v[tid];
    float bb = __ldg(bself + (tid & 127));
    __syncthreads();

    const uint32_t smem_u32 = (uint32_t)__cvta_generic_to_shared(sm);
    const float NEG_INF = __int_as_float(0xff800000);
    const int G = gridDim.x;

    int q = blockIdx.x;
    int s = 0;

    // ---- prologue: stage first quad ----
    prefetch_own(q, 0, rr, kq, lane, smem_u32, h_nei);
    cp_commit();
    // register-resident ego/mask for the first quad
    float4 egS_c = {0.f, 0.f, 0.f, 0.f};
    int    msk_c = 0;
    float  egp0_c = 0.f, egp1_c = 0.f;
    if (warp < 4) {
        egS_c = __ldg((const float4*)(h_ego + (size_t)q * 512 + warp * 128) + lane);
        msk_c = __ldg(nbr_mask + (size_t)q * 128 + warp * 32 + lane);
    }
    if (tid >= 256) {
        int t = tid - 256;
        egp0_c = __ldg(h_ego + (size_t)q * 512 + t);
        egp1_c = __ldg(h_ego + (size_t)q * 512 + t + 256);
    }

    for (; q < NQUAD; q += G, s ^= 1) {
        int qn = q + G;
        // issue next quad's cp.async into the other buffer (private region)
        if (qn < NQUAD) prefetch_own(qn, s ^ 1, rr, kq, lane, smem_u32, h_nei);
        cp_commit();
        // LDG-prefetch next quad's ego/mask into registers
        float4 egS_n = {0.f, 0.f, 0.f, 0.f};
        int    msk_n = 0;
        float  egp0_n = 0.f, egp1_n = 0.f;
        if (qn < NQUAD) {
            if (warp < 4) {
                egS_n = __ldg((const float4*)(h_ego + (size_t)qn * 512 + warp * 128) + lane);
                msk_n = __ldg(nbr_mask + (size_t)qn * 128 + warp * 32 + lane);
            }
            if (tid >= 256) {
                int t = tid - 256;
                egp0_n = __ldg(h_ego + (size_t)qn * 512 + t);
                egp1_n = __ldg(h_ego + (size_t)qn * 512 + t + 256);
            }
        }
        cp_wait1();   // current buffer's (own) fragments landed — NO barrier needed

        const float* hb = &sm[OFF_HN + s * 16384 + rr * 4096 + kq * 128];

        // ---- stage fragments (private, conflict-free) + raw neighbor dots ----
        float4 f0 = *(const float4*)&hb[0 * 128 + lane * 4];
        float4 f1 = *(const float4*)&hb[1 * 128 + lane * 4];
        float4 f2 = *(const float4*)&hb[2 * 128 + lane * 4];
        float4 f3 = *(const float4*)&hb[3 * 128 + lane * 4];
        float4 f4 = *(const float4*)&hb[4 * 128 + lane * 4];
        float4 f5 = *(const float4*)&hb[5 * 128 + lane * 4];
        float4 f6 = *(const float4*)&hb[6 * 128 + lane * 4];
        float4 f7 = *(const float4*)&hb[7 * 128 + lane * 4];
        {
            float4 vN = *(const float4*)&vs[D + lane * 4];
            float a0 = f0.x * vN.x + f0.y * vN.y + f0.z * vN.z + f0.w * vN.w;
            float a1 = f1.x * vN.x + f1.y * vN.y + f1.z * vN.z + f1.w * vN.w;
            float a2 = f2.x * vN.x + f2.y * vN.y + f2.z * vN.z + f2.w * vN.w;
            float a3 = f3.x * vN.x + f3.y * vN.y + f3.z * vN.z + f3.w * vN.w;
            float a4 = f4.x * vN.x + f4.y * vN.y + f4.z * vN.z + f4.w * vN.w;
            float a5 = f5.x * vN.x + f5.y * vN.y + f5.z * vN.z + f5.w * vN.w;
            float a6 = f6.x * vN.x + f6.y * vN.y + f6.z * vN.z + f6.w * vN.w;
            float a7 = f7.x * vN.x + f7.y * vN.y + f7.z * vN.z + f7.w * vN.w;
            #pragma unroll
            for (int o = 16; o > 0; o >>= 1) {
                a0 += __shfl_xor_sync(0xffffffffu, a0, o);
                a1 += __shfl_xor_sync(0xffffffffu, a1, o);
                a2 += __shfl_xor_sync(0xffffffffu, a2, o);
                a3 += __shfl_xor_sync(0xffffffffu, a3, o);
                a4 += __shfl_xor_sync(0xffffffffu, a4, o);
                a5 += __shfl_xor_sync(0xffffffffu, a5, o);
                a6 += __shfl_xor_sync(0xffffffffu, a6, o);
                a7 += __shfl_xor_sync(0xffffffffu, a7, o);
            }
            if (lane == 0) {
                float* lg = &logit[rr * KNBR + kq];
                lg[0] = a0; lg[1] = a1; lg[2] = a2; lg[3] = a3;
                lg[4] = a4; lg[5] = a5; lg[6] = a6; lg[7] = a7;
            }
        }
        // pack ego batch-major from prefetched registers (threads 256..511)
        if (tid >= 256) {
            int t = tid - 256;
            int r0i = t >> 7, dd0 = t & 127;                 // idx = t     (pair 0)
            ego2[2 * dd0 + (r0i & 1)] = egp0_c;
            int idx1 = t + 256;
            int r1i = idx1 >> 7, dd1 = idx1 & 127;           // idx = t+256 (pair 1)
            ego2[256 + 2 * dd1 + (r1i & 1)] = egp1_c;
        }
        __syncthreads();   // A1: logits + ego2 ready

        // ---- softmax (warps 0..3) || ego projection (warps 8..15) ----
        if (warp < 4) {
            float4 vE = *(const float4*)&vs[lane * 4];
            float pe = egS_c.x * vE.x + egS_c.y * vE.y + egS_c.z * vE.z + egS_c.w * vE.w;
            #pragma unroll
            for (int o = 16; o > 0; o >>= 1) pe += __shfl_xor_sync(0xffffffffu, pe, o);
            float x = logit[warp * KNBR + lane] + pe;
            x = (x > 0.f) ? x : 0.2f * x;                          // leaky_relu
            x = (msk_c > 0) ? x : NEG_INF;                         // mask
            float mx = x;
            #pragma unroll
            for (int o = 16; o > 0; o >>= 1) mx = fmaxf(mx, __shfl_xor_sync(0xffffffffu, mx, o));
            float ee = (x == NEG_INF) ? 0.f : __expf(x - mx);
            float ss = ee;
            #pragma unroll
            for (int o = 16; o > 0; o >>= 1) ss += __shfl_xor_sync(0xffffffffu, ss, o);
            attn[warp * KNBR + lane] = (ss > 0.f) ? (ee / ss) : 0.f;
        } else if (tid >= 256) {
            // ego @ Wself^T for both pairs — independent of attention
            const unsigned long long* xbase = (const unsigned long long*)ego2;
            unsigned long long* rE = (unsigned long long*)redE;
            proj64(xbase,       wreg, d0, &rE[0 * 512 + g * 128 + e]);
            proj64(xbase + 128, wreg, d0, &rE[1 * 512 + g * 128 + e]);
        }
        __syncthreads();   // A2: attn ready

        // ---- weighted partial aggregation from HELD registers ----
        {
            const float* at = &attn[rr * KNBR + kq];
            float a0 = at[0], a1 = at[1], a2 = at[2], a3 = at[3];
            float a4 = at[4], a5 = at[5], a6 = at[6], a7 = at[7];
            float4 acc;
            acc.x = a0 * f0.x; acc.y = a0 * f0.y; acc.z = a0 * f0.z; acc.w = a0 * f0.w;
            acc.x = fmaf(a1, f1.x, acc.x); acc.y = fmaf(a1, f1.y, acc.y);
            acc.z = fmaf(a1, f1.z, acc.z); acc.w = fmaf(a1, f1.w, acc.w);
            acc.x = fmaf(a2, f2.x, acc.x); acc.y = fmaf(a2, f2.y, acc.y);
            acc.z = fmaf(a2, f2.z, acc.z); acc.w = fmaf(a2, f2.w, acc.w);
            acc.x = fmaf(a3, f3.x, acc.x); acc.y = fmaf(a3, f3.y, acc.y);
            acc.z = fmaf(a3, f3.z, acc.z); acc.w = fmaf(a3, f3.w, acc.w);
            acc.x = fmaf(a4, f4.x, acc.x); acc.y = fmaf(a4, f4.y, acc.y);
            acc.z = fmaf(a4, f4.z, acc.z); acc.w = fmaf(a4, f4.w, acc.w);
            acc.x = fmaf(a5, f5.x, acc.x); acc.y = fmaf(a5, f5.y, acc.y);
            acc.z = fmaf(a5, f5.z, acc.z); acc.w = fmaf(a5, f5.w, acc.w);
            acc.x = fmaf(a6, f6.x, acc.x); acc.y = fmaf(a6, f6.y, acc.y);
            acc.z = fmaf(a6, f6.z, acc.z); acc.w = fmaf(a6, f6.w, acc.w);
            acc.x = fmaf(a7, f7.x, acc.x); acc.y = fmaf(a7, f7.y, acc.y);
            acc.z = fmaf(a7, f7.z, acc.z); acc.w = fmaf(a7, f7.w, acc.w);
            ((float4*)redD)[warp * 32 + lane] = acc;
        }
        __syncthreads();   // A3

        // ---- reduce 4 partials per (row,dim) -> batch-packed agg2 ----
        {
            int r  = tid >> 7;        // 0..3 (row)
            int dd = tid & 127;
            const float* rb = &redD[(4 * r) * 128 + dd];
            agg2[(r >> 1) * 256 + 2 * dd + (r & 1)] =
                rb[0] + rb[128] + rb[256] + rb[384];
        }
        __syncthreads();   // A4

        // ---- msg projection: agg @ Wmsg^T (threads 0..255) ----
        if (tid < 256) {
            const unsigned long long* xbase = (const unsigned long long*)agg2;
            unsigned long long* rE = (unsigned long long*)redE;
            proj64(xbase,       wreg, d0, &rE[0 * 512 + g * 128 + e]);
            proj64(xbase + 128, wreg, d0, &rE[1 * 512 + g * 128 + e]);
        }
        __syncthreads();   // A5

        // ---- combine + tanh + store (warps 0..7); warps 8..15 run ahead ----
        if (tid < 256) {
            int pr = tid >> 7, dd = tid & 127;
            const float2* r = (const float2*)redE + pr * 512;
            float2 r0 = r[0 * 128 + dd];
            float2 r1 = r[1 * 128 + dd];
            float2 r2 = r[2 * 128 + dd];
            float2 r3 = r[3 * 128 + dd];
            float o0 = tanhf(r0.x + r1.x + r2.x + r3.x + bb);
            float o1 = tanhf(r0.y + r1.y + r2.y + r3.y + bb);
            size_t row = ((size_t)4 * q + 2 * pr) * D;
            out[row + dd]     = o0;
            out[row + D + dd] = o1;
        }

        // rotate register-resident prefetches
        egS_c = egS_n; msk_c = msk_n; egp0_c = egp0_n; egp1_c = egp1_n;
    }
    cp_waitall();
}

// ---------------- launch ----------------
extern "C" void kernel_launch(void* const* d_in, const int* in_sizes, int n_in,
                              void* d_out, int out_size) {
    const float* h_ego  = (const float*)d_in[0];
    const float* h_nei  = (const float*)d_in[1];
    const int*   nmask  = (const int*)  d_in[2];
    const float* Wmsg   = (const float*)d_in[3];
    const float* Wattn  = (const float*)d_in[4];
    const float* Wself  = (const float*)d_in[5];
    const float* bself  = (const float*)d_in[6];
    float* out = (float*)d_out;

    int sms = 0;
    cudaDeviceGetAttribute(&sms, cudaDevAttrMultiProcessorCount, 0);
    if (sms <= 0) sms = 148;

    cudaFuncSetAttribute(gat_kernel, cudaFuncAttributeMaxDynamicSharedMemorySize, SMEM_BYTES);

    prep_kernel<<<1, D>>>(Wmsg, Wattn);
    gat_kernel<<<sms, T, SMEM_BYTES>>>(h_ego, h_nei, nmask, Wmsg, Wself, bself, out);
}

// round 8
// speedup vs baseline: 1.0243x; 1.0243x over previous
#include <cuda_runtime.h>
#include <cstdint>
#include <math.h>

#define KNBR  32
#define D     128
#define T     512
#define B_TOT 32768
#define NQUAD (B_TOT / 4)   // 4 rows (2 pairs) per macro-iteration

// smem layout (float offsets)
#define OFF_HN    0        // 2 * 16384 double-buffered (4 rows x 4096), thread-private regions
#define OFF_VS    32768    // 256 (v_ego | v_nbr)
#define OFF_EGO2  33024    // 512: ego2[pair*256 + 2*d + r]
#define OFF_AGG2  33536    // 512
#define OFF_REDD  34048    // 2048: 16 warps x 128
#define OFF_REDE  36096    // 2048: 2 pairs x 4 groups x 128 (float2)
#define OFF_LOG   38144    // 128
#define OFF_ATT   38272    // 128
#define SMEM_FLOATS 38400
#define SMEM_BYTES (SMEM_FLOATS * 4)

__device__ float g_v[2 * D];   // [0:128) v_ego = W_msg^T a_ego, [128:256) v_nbr

// ---------------- prologue: v = W_msg^T @ a ----------------
__global__ void prep_kernel(const float* __restrict__ Wmsg,
                            const float* __restrict__ Wattn) {
    int d = threadIdx.x;   // 128 threads
    float ve = 0.f, vn = 0.f;
    #pragma unroll 8
    for (int e = 0; e < D; e++) {
        float w = Wmsg[e * D + d];
        ve = fmaf(Wattn[e], w, ve);
        vn = fmaf(Wattn[D + e], w, vn);
    }
    g_v[d] = ve;
    g_v[D + d] = vn;
}

// ---------------- cp.async helpers ----------------
__device__ __forceinline__ void cp16(uint32_t dst, const void* src) {
    asm volatile("cp.async.cg.shared.global [%0], [%1], 16;" :: "r"(dst), "l"(src));
}
__device__ __forceinline__ void cp_commit() { asm volatile("cp.async.commit_group;"); }
__device__ __forceinline__ void cp_wait1()  { asm volatile("cp.async.wait_group 1;" ::: "memory"); }
__device__ __forceinline__ void cp_waitall(){ asm volatile("cp.async.wait_all;" ::: "memory"); }

// each thread copies EXACTLY the 8 fragments it will itself read later:
// rows (rr, kq..kq+7), column lane*4  -> producer == consumer, no CTA barrier
__device__ __forceinline__ void prefetch_own(int q, int buf, int rr, int kq, int lane,
                                             uint32_t smem_u32,
                                             const float* __restrict__ h_nei) {
    const float* src = h_nei + (size_t)q * 16384 + rr * 4096 + kq * 128 + lane * 4;
    uint32_t dst = smem_u32 +
        (uint32_t)(OFF_HN + buf * 16384 + rr * 4096 + kq * 128 + lane * 4) * 4u;
    #pragma unroll
    for (int i = 0; i < 8; i++)
        cp16(dst + (uint32_t)i * 512u, src + i * 128);
}

// ---------------- FFMA2 projection: 64 inputs, 2 rows packed, 4 acc chains ----------------
__device__ __forceinline__ void proj64(const unsigned long long* __restrict__ xq,
                                       const float* __restrict__ wreg,
                                       int d0, unsigned long long* dst) {
    unsigned long long acc0 = 0ull, acc1 = 0ull, acc2 = 0ull, acc3 = 0ull;
    #pragma unroll
    for (int j = 0; j < 64; j += 8) {
        #define PROJ_STEP(JJ, ACC) { \
            ulonglong2 xx = *(const ulonglong2*)&xq[d0 + (JJ)]; \
            unsigned long long w0, w1; \
            unsigned int wa = __float_as_uint(wreg[(JJ)]); \
            unsigned int wb = __float_as_uint(wreg[(JJ) + 1]); \
            asm("mov.b64 %0, {%1,%1};" : "=l"(w0) : "r"(wa)); \
            asm("mov.b64 %0, {%1,%1};" : "=l"(w1) : "r"(wb)); \
            asm("fma.rn.f32x2 %0, %1, %2, %3;" : "=l"(ACC) : "l"(w0), "l"(xx.x), "l"(ACC)); \
            asm("fma.rn.f32x2 %0, %1, %2, %3;" : "=l"(ACC) : "l"(w1), "l"(xx.y), "l"(ACC)); }
        PROJ_STEP(j,     acc0)
        PROJ_STEP(j + 2, acc1)
        PROJ_STEP(j + 4, acc2)
        PROJ_STEP(j + 6, acc3)
        #undef PROJ_STEP
    }
    asm("add.rn.f32x2 %0, %1, %2;" : "=l"(acc0) : "l"(acc0), "l"(acc1));
    asm("add.rn.f32x2 %0, %1, %2;" : "=l"(acc2) : "l"(acc2), "l"(acc3));
    asm("add.rn.f32x2 %0, %1, %2;" : "=l"(acc0) : "l"(acc0), "l"(acc2));
    *dst = acc0;
}

// ---------------- main fused kernel ----------------
__global__ void __launch_bounds__(T, 1)
gat_kernel(const float* __restrict__ h_ego, const float* __restrict__ h_nei,
           const int*   __restrict__ nbr_mask,
           const float* __restrict__ Wmsg, const float* __restrict__ Wself,
           const float* __restrict__ bself, float* __restrict__ out) {
    extern __shared__ float sm[];
    float* vs    = sm + OFF_VS;
    float* ego2  = sm + OFF_EGO2;
    float* agg2  = sm + OFF_AGG2;
    float* redD  = sm + OFF_REDD;
    float* redE  = sm + OFF_REDE;
    float* logit = sm + OFF_LOG;
    float* attn  = sm + OFF_ATT;

    const int tid  = threadIdx.x;
    const int lane = tid & 31;
    const int warp = tid >> 5;
    const int g    = tid >> 7;            // 0..3: {Wmsg-lo, Wmsg-hi, Wself-lo, Wself-hi}
    const int e    = tid & 127;
    const int d0   = (g & 1) * 64;        // input-dim half
    const int rr   = warp >> 2;           // row within quad (0..3)
    const int kq   = (warp & 3) * 8;      // 8 k's per warp

    // W slice in registers
    const float* Wsrc = (g < 2) ? Wmsg : Wself;
    float wreg[64];
    #pragma unroll
    for (int j = 0; j < 64; j += 4) {
        float4 t4 = *(const float4*)&Wsrc[e * D + d0 + j];
        wreg[j] = t4.x; wreg[j + 1] = t4.y; wreg[j + 2] = t4.z; wreg[j + 3] = t4.w;
    }
    if (tid < 2 * D) vs[tid] = g_v[tid];
    float bb = __ldg(bself + (tid & 127));
    __syncthreads();

    const uint32_t smem_u32 = (uint32_t)__cvta_generic_to_shared(sm);
    const float NEG_INF = __int_as_float(0xff800000);
    const int G = gridDim.x;

    int q = blockIdx.x;
    int s = 0;

    // ---- prologue: stage first quad (private regions) ----
    if (q < NQUAD) prefetch_own(q, 0, rr, kq, lane, smem_u32, h_nei);
    cp_commit();

    for (; q < NQUAD; q += G, s ^= 1) {
        int qn = q + G;
        // issue next quad's cp.async into the other (private) buffer
        if (qn < NQUAD) prefetch_own(qn, s ^ 1, rr, kq, lane, smem_u32, h_nei);
        cp_commit();

        // ---- per-iteration LDG of ego/mask (consumed after dot work -> hidden) ----
        float4 egS = {0.f, 0.f, 0.f, 0.f};
        int    mk  = 0;
        float  egp0 = 0.f, egp1 = 0.f;
        if (warp < 4) {
            egS = __ldg((const float4*)(h_ego + (size_t)q * 512 + warp * 128) + lane);
            mk  = __ldg(nbr_mask + (size_t)q * 128 + warp * 32 + lane);
        }
        if (tid >= 256) {
            int t = tid - 256;
            egp0 = __ldg(h_ego + (size_t)q * 512 + t);
            egp1 = __ldg(h_ego + (size_t)q * 512 + t + 256);
        }

        cp_wait1();   // own fragments landed — producer==consumer, no barrier

        const float* hb = &sm[OFF_HN + s * 16384 + rr * 4096 + kq * 128];

        // ---- stage fragments (private, conflict-free) + raw neighbor dots ----
        float4 f0 = *(const float4*)&hb[0 * 128 + lane * 4];
        float4 f1 = *(const float4*)&hb[1 * 128 + lane * 4];
        float4 f2 = *(const float4*)&hb[2 * 128 + lane * 4];
        float4 f3 = *(const float4*)&hb[3 * 128 + lane * 4];
        float4 f4 = *(const float4*)&hb[4 * 128 + lane * 4];
        float4 f5 = *(const float4*)&hb[5 * 128 + lane * 4];
        float4 f6 = *(const float4*)&hb[6 * 128 + lane * 4];
        float4 f7 = *(const float4*)&hb[7 * 128 + lane * 4];
        {
            float4 vN = *(const float4*)&vs[D + lane * 4];
            float a0 = f0.x * vN.x + f0.y * vN.y + f0.z * vN.z + f0.w * vN.w;
            float a1 = f1.x * vN.x + f1.y * vN.y + f1.z * vN.z + f1.w * vN.w;
            float a2 = f2.x * vN.x + f2.y * vN.y + f2.z * vN.z + f2.w * vN.w;
            float a3 = f3.x * vN.x + f3.y * vN.y + f3.z * vN.z + f3.w * vN.w;
            float a4 = f4.x * vN.x + f4.y * vN.y + f4.z * vN.z + f4.w * vN.w;
            float a5 = f5.x * vN.x + f5.y * vN.y + f5.z * vN.z + f5.w * vN.w;
            float a6 = f6.x * vN.x + f6.y * vN.y + f6.z * vN.z + f6.w * vN.w;
            float a7 = f7.x * vN.x + f7.y * vN.y + f7.z * vN.z + f7.w * vN.w;
            #pragma unroll
            for (int o = 16; o > 0; o >>= 1) {
                a0 += __shfl_xor_sync(0xffffffffu, a0, o);
                a1 += __shfl_xor_sync(0xffffffffu, a1, o);
                a2 += __shfl_xor_sync(0xffffffffu, a2, o);
                a3 += __shfl_xor_sync(0xffffffffu, a3, o);
                a4 += __shfl_xor_sync(0xffffffffu, a4, o);
                a5 += __shfl_xor_sync(0xffffffffu, a5, o);
                a6 += __shfl_xor_sync(0xffffffffu, a6, o);
                a7 += __shfl_xor_sync(0xffffffffu, a7, o);
            }
            if (lane == 0) {
                float* lg = &logit[rr * KNBR + kq];
                lg[0] = a0; lg[1] = a1; lg[2] = a2; lg[3] = a3;
                lg[4] = a4; lg[5] = a5; lg[6] = a6; lg[7] = a7;
            }
        }
        // pack ego batch-major from the LDG values (threads 256..511)
        if (tid >= 256) {
            int t = tid - 256;
            int r0i = t >> 7, dd0 = t & 127;                 // idx = t     (pair 0)
            ego2[2 * dd0 + (r0i & 1)] = egp0;
            int idx1 = t + 256;
            int r1i = idx1 >> 7, dd1 = idx1 & 127;           // idx = t+256 (pair 1)
            ego2[256 + 2 * dd1 + (r1i & 1)] = egp1;
        }
        __syncthreads();   // A1: logits + ego2 ready

        // ---- softmax (warps 0..3) || ego projection (warps 8..15) ----
        if (warp < 4) {
            float4 vE = *(const float4*)&vs[lane * 4];
            float pe = egS.x * vE.x + egS.y * vE.y + egS.z * vE.z + egS.w * vE.w;
            #pragma unroll
            for (int o = 16; o > 0; o >>= 1) pe += __shfl_xor_sync(0xffffffffu, pe, o);
            float x = logit[warp * KNBR + lane] + pe;
            x = (x > 0.f) ? x : 0.2f * x;                          // leaky_relu
            x = (mk > 0) ? x : NEG_INF;                            // mask
            float mx = x;
            #pragma unroll
            for (int o = 16; o > 0; o >>= 1) mx = fmaxf(mx, __shfl_xor_sync(0xffffffffu, mx, o));
            float ee = (x == NEG_INF) ? 0.f : __expf(x - mx);
            float ss = ee;
            #pragma unroll
            for (int o = 16; o > 0; o >>= 1) ss += __shfl_xor_sync(0xffffffffu, ss, o);
            attn[warp * KNBR + lane] = (ss > 0.f) ? (ee / ss) : 0.f;
        } else if (tid >= 256) {
            // ego @ Wself^T for both pairs — independent of attention
            const unsigned long long* xbase = (const unsigned long long*)ego2;
            unsigned long long* rE = (unsigned long long*)redE;
            proj64(xbase,       wreg, d0, &rE[0 * 512 + g * 128 + e]);
            proj64(xbase + 128, wreg, d0, &rE[1 * 512 + g * 128 + e]);
        }
        __syncthreads();   // A2: attn ready

        // ---- weighted partial aggregation from HELD registers ----
        {
            const float* at = &attn[rr * KNBR + kq];
            float a0 = at[0], a1 = at[1], a2 = at[2], a3 = at[3];
            float a4 = at[4], a5 = at[5], a6 = at[6], a7 = at[7];
            float4 acc;
            acc.x = a0 * f0.x; acc.y = a0 * f0.y; acc.z = a0 * f0.z; acc.w = a0 * f0.w;
            acc.x = fmaf(a1, f1.x, acc.x); acc.y = fmaf(a1, f1.y, acc.y);
            acc.z = fmaf(a1, f1.z, acc.z); acc.w = fmaf(a1, f1.w, acc.w);
            acc.x = fmaf(a2, f2.x, acc.x); acc.y = fmaf(a2, f2.y, acc.y);
            acc.z = fmaf(a2, f2.z, acc.z); acc.w = fmaf(a2, f2.w, acc.w);
            acc.x = fmaf(a3, f3.x, acc.x); acc.y = fmaf(a3, f3.y, acc.y);
            acc.z = fmaf(a3, f3.z, acc.z); acc.w = fmaf(a3, f3.w, acc.w);
            acc.x = fmaf(a4, f4.x, acc.x); acc.y = fmaf(a4, f4.y, acc.y);
            acc.z = fmaf(a4, f4.z, acc.z); acc.w = fmaf(a4, f4.w, acc.w);
            acc.x = fmaf(a5, f5.x, acc.x); acc.y = fmaf(a5, f5.y, acc.y);
            acc.z = fmaf(a5, f5.z, acc.z); acc.w = fmaf(a5, f5.w, acc.w);
            acc.x = fmaf(a6, f6.x, acc.x); acc.y = fmaf(a6, f6.y, acc.y);
            acc.z = fmaf(a6, f6.z, acc.z); acc.w = fmaf(a6, f6.w, acc.w);
            acc.x = fmaf(a7, f7.x, acc.x); acc.y = fmaf(a7, f7.y, acc.y);
            acc.z = fmaf(a7, f7.z, acc.z); acc.w = fmaf(a7, f7.w, acc.w);
            ((float4*)redD)[warp * 32 + lane] = acc;
        }
        __syncthreads();   // A3

        // ---- reduce 4 partials per (row,dim) -> batch-packed agg2 ----
        {
            int r  = tid >> 7;        // 0..3 (row)
            int dd = tid & 127;
            const float* rb = &redD[(4 * r) * 128 + dd];
            agg2[(r >> 1) * 256 + 2 * dd + (r & 1)] =
                rb[0] + rb[128] + rb[256] + rb[384];
        }
        __syncthreads();   // A4

        // ---- msg projection: agg @ Wmsg^T (threads 0..255) ----
        if (tid < 256) {
            const unsigned long long* xbase = (const unsigned long long*)agg2;
            unsigned long long* rE = (unsigned long long*)redE;
            proj64(xbase,       wreg, d0, &rE[0 * 512 + g * 128 + e]);
            proj64(xbase + 128, wreg, d0, &rE[1 * 512 + g * 128 + e]);
        }
        __syncthreads();   // A5

        // ---- combine + tanh + store (warps 0..7); warps 8..15 run ahead ----
        if (tid < 256) {
            int pr = tid >> 7, dd = tid & 127;
            const float2* r = (const float2*)redE + pr * 512;
            float2 r0 = r[0 * 128 + dd];
            float2 r1 = r[1 * 128 + dd];
            float2 r2 = r[2 * 128 + dd];
            float2 r3 = r[3 * 128 + dd];
            float o0 = tanhf(r0.x + r1.x + r2.x + r3.x + bb);
            float o1 = tanhf(r0.y + r1.y + r2.y + r3.y + bb);
            size_t row = ((size_t)4 * q + 2 * pr) * D;
            out[row + dd]     = o0;
            out[row + D + dd] = o1;
        }
    }
    cp_waitall();
}

// ---------------- launch ----------------
extern "C" void kernel_launch(void* const* d_in, const int* in_sizes, int n_in,
                              void* d_out, int out_size) {
    const float* h_ego  = (const float*)d_in[0];
    const float* h_nei  = (const float*)d_in[1];
    const int*   nmask  = (const int*)  d_in[2];
    const float* Wmsg   = (const float*)d_in[3];
    const float* Wattn  = (const float*)d_in[4];
    const float* Wself  = (const float*)d_in[5];
    const float* bself  = (const float*)d_in[6];
    float* out = (float*)d_out;

    int sms = 0;
    cudaDeviceGetAttribute(&sms, cudaDevAttrMultiProcessorCount, 0);
    if (sms <= 0) sms = 148;

    cudaFuncSetAttribute(gat_kernel, cudaFuncAttributeMaxDynamicSharedMemorySize, SMEM_BYTES);

    prep_kernel<<<1, D>>>(Wmsg, Wattn);
    gat_kernel<<<sms, T, SMEM_BYTES>>>(h_ego, h_nei, nmask, Wmsg, Wself, bself, out);
}